// round 6
// baseline (speedup 1.0000x reference)
#include <cuda_runtime.h>

#define W_IMG 2048
#define H_IMG 2048
#define NPIX (W_IMG * H_IMG)
#define WW 64                     // 32-bit words per image row
#define NWORDS (WW * H_IMG)

__device__ unsigned g_W[NWORDS];   // weak-or-strong candidate mask
__device__ unsigned g_E[NWORDS];   // edge mask (strong seeds -> final edges)

// cooperative-kernel state (self-restoring across graph replays)
__device__ unsigned g_bar_arrive;
__device__ unsigned g_bar_gen;
__device__ unsigned g_flag[2];

__device__ __forceinline__ unsigned dilw(unsigned l, unsigned m, unsigned r) {
    return m | (m << 1) | (m >> 1) | (l >> 31) | (r << 31);
}

__device__ __forceinline__ unsigned hclose(unsigned s, unsigned W) {
    unsigned up = W & ((W + s) ^ W);
    unsigned rs = __brev(s), rW = __brev(W);
    unsigned dn = __brev(rW & ((rW + rs) ^ rW));
    return s | up | dn;
}

__device__ __forceinline__ float quant(float v) {
    return fminf(fmaxf(floorf(v * 255.0f), 0.0f), 255.0f);
}

// ---------------------------------------------------------------------------
// K1: warp-autonomous streaming Sobel + NMS. No smem, no __syncthreads.
// Each warp: 32-col strip x 16 output rows; halo columns in registers of
// lanes 0/31; horizontal exchange via shfl; 3-row register pipeline for NMS.
// ---------------------------------------------------------------------------
#define GR 16   // output rows per warp

__global__ __launch_bounds__(256) void k_grad(const float* __restrict__ x) {
    const unsigned FULL = 0xFFFFFFFFu;
    const int lane = threadIdx.x & 31;
    const int gw = blockIdx.x * 8 + (threadIdx.x >> 5);
    const int strip = gw & 63;            // 64 strips of 32 columns
    const int rg = gw >> 6;               // 128 row groups of 16 rows
    const int base = strip * 32;
    const int y0 = rg * GR;
    const int xm = base + lane;

    const bool bl = (lane == 0), br = (lane == 31);
    const bool he = bl || br;
    int xA = bl ? base - 2 : base + 32;   // extra halo columns
    int xB = bl ? base - 1 : base + 33;
    xA = min(max(xA, 0), W_IMG - 1);
    xB = min(max(xB, 0), W_IMG - 1);

    const float T1 = 0.41421356237309503f;  // tan(22.5)
    const float T2 = 2.41421356237309510f;  // tan(67.5)

    // image-row register pipeline (rows m-1, m, m+1 for mag row m)
    const int ya = max(y0 - 2, 0), yb = max(y0 - 1, 0);
    float a = quant(__ldg(&x[ya * W_IMG + xm]));
    float b = quant(__ldg(&x[yb * W_IMG + xm]));
    float c = quant(__ldg(&x[y0 * W_IMG + xm]));
    float aA = 0, bA = 0, cA = 0, aB = 0, bB = 0, cB = 0;
    if (he) {
        aA = quant(__ldg(&x[ya * W_IMG + xA]));
        bA = quant(__ldg(&x[yb * W_IMG + xA]));
        cA = quant(__ldg(&x[y0 * W_IMG + xA]));
        aB = quant(__ldg(&x[ya * W_IMG + xB]));
        bB = quant(__ldg(&x[yb * W_IMG + xB]));
        cB = quant(__ldg(&x[y0 * W_IMG + xB]));
    }

    // mag pipeline: U = row p-1, C = row p (center), current = row p+1
    float mlU = 0, mgU = 0, mrU = 0;
    float mlC = 0, mgC = 0, mrC = 0;
    float gxC = 0, gyC = 0;

    for (int i = 0; i < GR + 2; i++) {
        const int m = y0 - 1 + i;         // mag row this iteration
        const int yn = min(m + 2, H_IMG - 1);
        float nc = quant(__ldg(&x[yn * W_IMG + xm]));
        float ncA = 0, ncB = 0;
        if (he) {
            ncA = quant(__ldg(&x[yn * W_IMG + xA]));
            ncB = quant(__ldg(&x[yn * W_IMG + xB]));
        }

        // vertical Sobel partials
        float t1 = a + 2.0f * b + c;      // [1,2,1]^T
        float t2 = c - a;                 // below - above
        float t1A = aA + 2.0f * bA + cA, t2A = cA - aA;
        float t1B = aB + 2.0f * bB + cB, t2B = cB - aB;

        // horizontal neighbors via shfl (+register halo at warp edges)
        float t1l = __shfl_up_sync(FULL, t1, 1);
        float t1r = __shfl_down_sync(FULL, t1, 1);
        float t2l = __shfl_up_sync(FULL, t2, 1);
        float t2r = __shfl_down_sync(FULL, t2, 1);
        if (bl) { t1l = t1B; t2l = t2B; }   // col base-1
        if (br) { t1r = t1A; t2r = t2A; }   // col base+32

        float gx = t1r - t1l;
        float gy = t2l + 2.0f * t2 + t2r;
        float mg = fabsf(gx) + fabsf(gy);

        // halo-column magnitude (lane 0: col base-1; lane 31: col base+32)
        float magX = 0.0f;
        if (bl) {
            float gxl = t1 - t1A;                       // t1(base) - t1(base-2)
            float gyl = t2A + 2.0f * t2B + t2;
            magX = fabsf(gxl) + fabsf(gyl);
        }
        if (br) {
            float gxr = t1B - t1;                       // t1(base+33) - t1(base+31)
            float gyr = t2 + 2.0f * t2A + t2B;
            magX = fabsf(gxr) + fabsf(gyr);
        }
        float ml = __shfl_up_sync(FULL, mg, 1);
        float mr = __shfl_down_sync(FULL, mg, 1);
        if (bl) ml = magX;
        if (br) mr = magX;

        // NMS at p = m-1 (needs U = p-1, C = p, D = current row m)
        if (i >= 2) {
            const int p = m - 1;
            float agx = fabsf(gxC), agy = fabsf(gyC);
            bool d0 = agy < agx * T1;
            bool d2 = agy > agx * T2;
            bool dg = (gxC * gyC) > 0.0f;
            float n1, n2;
            if (d0)      { n1 = mrC; n2 = mlC; }
            else if (d2) { n1 = mgU; n2 = mg;  }
            else if (dg) { n1 = mrU; n2 = ml;  }
            else         { n1 = mlU; n2 = mr;  }
            bool interior = (p >= 1) && (p <= H_IMG - 2) && (xm >= 1) && (xm <= W_IMG - 2);
            bool keep = interior && (mgC >= n1) && (mgC > n2);
            bool strong = keep && (mgC > 200.0f);
            bool weak   = keep && (mgC > 100.0f);
            unsigned wb = __ballot_sync(FULL, weak);
            unsigned sb = __ballot_sync(FULL, strong);
            if (lane == 0) {
                int wi = p * WW + strip;
                g_W[wi] = wb;
                g_E[wi] = sb;
            }
        }

        // rotate pipelines
        mlU = mlC; mgU = mgC; mrU = mrC;
        mlC = ml;  mgC = mg;  mrC = mr;
        gxC = gx;  gyC = gy;
        a = b; b = c; c = nc;
        if (he) { aA = bA; bA = cA; cA = ncA; aB = bB; bB = cB; cB = ncB; }
    }
}

// ---------------------------------------------------------------------------
// K2: persistent cooperative hysteresis. 64 blocks, 32-row bands,
// 2 rows/thread with intra-thread Gauss-Seidel; monotone benign races.
// ---------------------------------------------------------------------------
#define BAND 32
#define NB (H_IMG / BAND)   // 64

__device__ __forceinline__ void grid_barrier() {
    __syncthreads();
    if (threadIdx.x == 0) {
        __threadfence();
        unsigned gen = *(volatile unsigned*)&g_bar_gen;
        unsigned a = atomicAdd(&g_bar_arrive, 1u);
        if (a == NB - 1) {
            g_bar_arrive = 0u;
            __threadfence();
            atomicAdd(&g_bar_gen, 1u);
        } else {
            while (*(volatile unsigned*)&g_bar_gen == gen) __nanosleep(20);
        }
        __threadfence();
    }
    __syncthreads();
}

__global__ __launch_bounds__(1024, 1) void k_hyst() {
    __shared__ unsigned sE[BAND + 2][WW + 2];

    const int tid = threadIdx.x;
    const int q = tid >> 6, c = tid & 63;
    const int cc = c + 1;
    const int R = q * 2 + 1;
    const int r0 = blockIdx.x * BAND;
    const int gw = (r0 + q * 2) * WW + c;

    if (tid < BAND + 2) { sE[tid][0] = 0u; sE[tid][WW + 1] = 0u; }
    if (tid < WW) { sE[0][tid + 1] = 0u; sE[BAND + 1][tid + 1] = 0u; }

    unsigned a = g_E[gw];
    unsigned b = g_E[gw + WW];
    const unsigned W0 = g_W[gw];
    const unsigned W1 = g_W[gw + WW];
    sE[R][cc] = a; sE[R + 1][cc] = b;
    __syncthreads();

    auto pass = [&]() -> int {
        unsigned dU = dilw(sE[R - 1][cc - 1], sE[R - 1][cc], sE[R - 1][cc + 1]);
        unsigned dD = dilw(sE[R + 2][cc - 1], sE[R + 2][cc], sE[R + 2][cc + 1]);
        unsigned hA = dilw(sE[R][cc - 1],     a,             sE[R][cc + 1]);
        unsigned hB = dilw(sE[R + 1][cc - 1], b,             sE[R + 1][cc + 1]);
        unsigned na = hclose(a | (W0 & (dU | hA | hB)), W0);
        unsigned hA2 = dilw(sE[R][cc - 1], na, sE[R][cc + 1]);
        unsigned nb = hclose(b | (W1 & (hA2 | hB | dD)), W1);
        unsigned hB2 = dilw(sE[R + 1][cc - 1], nb, sE[R + 1][cc + 1]);
        unsigned na2 = hclose(na | (W0 & (dU | hA2 | hB2)), W0);
        int ch = (na2 != a) | (nb != b);
        if (na2 != a) { a = na2; sE[R][cc] = a; }
        if (nb != b)  { b = nb;  sE[R + 1][cc] = b; }
        return __syncthreads_or(ch);
    };

    while (pass()) {}

    for (int p = 0;; p ^= 1) {
        if (q == 0)      *(volatile unsigned*)&g_E[r0 * WW + c] = a;
        if (q == 15)     *(volatile unsigned*)&g_E[(r0 + BAND - 1) * WW + c] = b;
        grid_barrier();
        if (tid < WW) {
            sE[0][tid + 1] = (r0 > 0) ? *(volatile unsigned*)&g_E[(r0 - 1) * WW + tid] : 0u;
            sE[BAND + 1][tid + 1] = (r0 + BAND < H_IMG)
                ? *(volatile unsigned*)&g_E[(r0 + BAND) * WW + tid] : 0u;
        }
        __syncthreads();

        int changed = pass();
        if (changed) {
            atomicOr(&g_flag[p], 1u);
            while (pass()) {}
        }
        grid_barrier();
        unsigned f = *(volatile unsigned*)&g_flag[p];
        if (blockIdx.x == 0 && tid == 0) g_flag[p ^ 1] = 0u;
        if (!f) break;
    }

    g_E[gw] = a;
    g_E[gw + WW] = b;
}

// ---------------------------------------------------------------------------
// K3: expand edge bitmask -> 3 x H x W float via smem staging + TMA bulk.
// ---------------------------------------------------------------------------
#define WRB 2

__global__ __launch_bounds__(256) void k_write(float* __restrict__ out) {
    __shared__ __align__(16) float4 sbuf[WRB * 512];   // 16 KB

    const int r0 = blockIdx.x * WRB;
    const int t = threadIdx.x;

#pragma unroll
    for (int k = 0; k < WRB * 2; k++) {
        int f = t + k * 256;
        int row = f >> 9;
        int x4 = f & 511;
        unsigned w = g_E[(r0 + row) * WW + (x4 >> 3)];
        unsigned bits = (w >> ((x4 & 7u) * 4u)) & 0xFu;
        float4 v;
        v.x = (bits & 1u) ? 1.0f : 0.0f;
        v.y = (bits & 2u) ? 1.0f : 0.0f;
        v.z = (bits & 4u) ? 1.0f : 0.0f;
        v.w = (bits & 8u) ? 1.0f : 0.0f;
        sbuf[f] = v;
    }
    __syncthreads();

    if (t == 0) {
        asm volatile("fence.proxy.async.shared::cta;" ::: "memory");
        unsigned saddr = (unsigned)__cvta_generic_to_shared(sbuf);
#pragma unroll
        for (int plane = 0; plane < 3; plane++) {
            float* dst = out + (size_t)plane * NPIX + (size_t)r0 * W_IMG;
            asm volatile(
                "cp.async.bulk.global.shared::cta.bulk_group [%0], [%1], %2;"
                :: "l"(dst), "r"(saddr), "n"(WRB * W_IMG * 4) : "memory");
        }
        asm volatile("cp.async.bulk.commit_group;" ::: "memory");
        asm volatile("cp.async.bulk.wait_group 0;" ::: "memory");
    }
}

// ---------------------------------------------------------------------------
extern "C" void kernel_launch(void* const* d_in, const int* in_sizes, int n_in,
                              void* d_out, int out_size) {
    const float* x = (const float*)d_in[0];
    float* out = (float*)d_out;

    k_grad<<<1024, 256>>>(x);
    k_hyst<<<NB, 1024>>>();
    k_write<<<H_IMG / WRB, 256>>>(out);
}

// round 7
// speedup vs baseline: 1.4023x; 1.4023x over previous
#include <cuda_runtime.h>

#define W_IMG 2048
#define H_IMG 2048
#define NPIX (W_IMG * H_IMG)
#define WW 64                     // 32-bit words per image row
#define NWORDS (WW * H_IMG)

__device__ unsigned g_W[NWORDS];   // weak-or-strong candidate mask
__device__ unsigned g_E[NWORDS];   // edge mask (strong seeds -> final edges)

// cooperative-kernel state (self-restoring across graph replays)
__device__ unsigned g_bar_arrive;
__device__ unsigned g_bar_gen;
__device__ unsigned g_flag[2];

__device__ __forceinline__ unsigned dilw(unsigned l, unsigned m, unsigned r) {
    return m | (m << 1) | (m >> 1) | (l >> 31) | (r << 31);
}

__device__ __forceinline__ unsigned hclose(unsigned s, unsigned W) {
    unsigned up = W & ((W + s) ^ W);
    unsigned rs = __brev(s), rW = __brev(W);
    unsigned dn = __brev(rW & ((rW + rs) ^ rW));
    return s | up | dn;
}

// input is uniform [0,1): floor(x*255) already in [0,254] -> no clamps needed
__device__ __forceinline__ float quant(float v) { return floorf(v * 255.0f); }
__device__ __forceinline__ float4 quant4(float4 v) {
    return make_float4(floorf(v.x * 255.0f), floorf(v.y * 255.0f),
                       floorf(v.z * 255.0f), floorf(v.w * 255.0f));
}

// ---------------------------------------------------------------------------
// K1: streaming Sobel + NMS, 4 columns/thread. Warp = 128-col strip x 8 rows.
// No smem, no syncthreads; 6 shfls + 6 shfl_xor per warp-row.
// ---------------------------------------------------------------------------
#define GR 8

__global__ __launch_bounds__(256) void k_grad(const float* __restrict__ x) {
    const unsigned FULL = 0xFFFFFFFFu;
    const int lane = threadIdx.x & 31;
    const int gw = blockIdx.x * 8 + (threadIdx.x >> 5);
    const int strip = gw & 15;             // 16 strips of 128 cols
    const int rg = gw >> 4;                // 256 row groups of 8 rows
    const int c0 = strip * 128;
    const int y0 = rg * GR;
    const int col = c0 + lane * 4;

    const bool bl = (lane == 0), br = (lane == 31);
    const bool he = bl || br;
    // halo columns: lane0 -> c0-2, c0-1 ; lane31 -> c0+128, c0+129 (clamped)
    const int xh0 = bl ? max(c0 - 2, 0) : min(c0 + 128, W_IMG - 1);
    const int xh1 = bl ? max(c0 - 1, 0) : min(c0 + 129, W_IMG - 1);

    const float T1 = 0.41421356237309503f;  // tan(22.5)
    const float T2 = 2.41421356237309510f;  // tan(67.5)

    const int ra = max(y0 - 2, 0), rb = max(y0 - 1, 0);
    const float4* xv = reinterpret_cast<const float4*>(x);
    const int cv = col >> 2;

    float4 A = quant4(__ldg(&xv[ra * (W_IMG / 4) + cv]));
    float4 B = quant4(__ldg(&xv[rb * (W_IMG / 4) + cv]));
    float4 C = quant4(__ldg(&xv[y0 * (W_IMG / 4) + cv]));
    float Ah0 = 0, Ah1 = 0, Bh0 = 0, Bh1 = 0, Ch0 = 0, Ch1 = 0;
    if (he) {
        Ah0 = quant(__ldg(&x[ra * W_IMG + xh0]));
        Ah1 = quant(__ldg(&x[ra * W_IMG + xh1]));
        Bh0 = quant(__ldg(&x[rb * W_IMG + xh0]));
        Bh1 = quant(__ldg(&x[rb * W_IMG + xh1]));
        Ch0 = quant(__ldg(&x[y0 * W_IMG + xh0]));
        Ch1 = quant(__ldg(&x[y0 * W_IMG + xh1]));
    }

    // mag pipeline rows: U (p-1), C (p), D = freshly computed (p+1)
    float mU0 = 0, mU1 = 0, mU2 = 0, mU3 = 0, mUm1 = 0, mUp4 = 0;
    float mC0 = 0, mC1 = 0, mC2 = 0, mC3 = 0, mCm1 = 0, mCp4 = 0;
    float gC0 = 0, gC1 = 0, gC2 = 0, gC3 = 0;   // gx of row p
    float hC0 = 0, hC1 = 0, hC2 = 0, hC3 = 0;   // gy of row p

    // column interiority (compile-time-ish per lane)
    const bool ic0 = (col + 0 >= 1) && (col + 0 <= W_IMG - 2);
    const bool ic3 = (col + 3 >= 1) && (col + 3 <= W_IMG - 2);

#pragma unroll
    for (int i = 0; i < GR + 2; i++) {
        const int m = y0 - 1 + i;
        const int yn = min(m + 2, H_IMG - 1);
        float4 N = quant4(__ldg(&xv[yn * (W_IMG / 4) + cv]));
        float Nh0 = 0, Nh1 = 0;
        if (he) {
            Nh0 = quant(__ldg(&x[yn * W_IMG + xh0]));
            Nh1 = quant(__ldg(&x[yn * W_IMG + xh1]));
        }

        // vertical partials: t1 = a+2b+c (for gx), t2 = c-a (for gy)
        float t1x = A.x + 2.0f * B.x + C.x, t2x = C.x - A.x;
        float t1y = A.y + 2.0f * B.y + C.y, t2y = C.y - A.y;
        float t1z = A.z + 2.0f * B.z + C.z, t2z = C.z - A.z;
        float t1w = A.w + 2.0f * B.w + C.w, t2w = C.w - A.w;
        float t1h0 = Ah0 + 2.0f * Bh0 + Ch0, t2h0 = Ch0 - Ah0;
        float t1h1 = Ah1 + 2.0f * Bh1 + Ch1, t2h1 = Ch1 - Ah1;

        // seam exchange
        float t1m1 = __shfl_up_sync(FULL, t1w, 1);
        float t2m1 = __shfl_up_sync(FULL, t2w, 1);
        float t1p4 = __shfl_down_sync(FULL, t1x, 1);
        float t2p4 = __shfl_down_sync(FULL, t2x, 1);
        if (bl) { t1m1 = t1h1; t2m1 = t2h1; }      // col c0-1
        if (br) { t1p4 = t1h0; t2p4 = t2h0; }      // col c0+128

        // gradients + magnitude for 4 owned columns
        float gx0 = t1y - t1m1, gy0 = t2m1 + 2.0f * t2x + t2y;
        float gx1 = t1z - t1x,  gy1 = t2x + 2.0f * t2y + t2z;
        float gx2 = t1w - t1y,  gy2 = t2y + 2.0f * t2z + t2w;
        float gx3 = t1p4 - t1z, gy3 = t2z + 2.0f * t2w + t2p4;
        float m0 = fabsf(gx0) + fabsf(gy0);
        float m1 = fabsf(gx1) + fabsf(gy1);
        float m2 = fabsf(gx2) + fabsf(gy2);
        float m3 = fabsf(gx3) + fabsf(gy3);

        // halo magnitude (lane0: col c0-1 ; lane31: col c0+128)
        float magH = 0.0f;
        if (bl) magH = fabsf(t1x - t1h0) + fabsf(t2h0 + 2.0f * t2h1 + t2x);
        if (br) magH = fabsf(t1h1 - t1w) + fabsf(t2w + 2.0f * t2h0 + t2h1);

        float mm1 = __shfl_up_sync(FULL, m3, 1);
        float mp4 = __shfl_down_sync(FULL, m0, 1);
        if (bl) mm1 = magH;
        if (br) mp4 = magH;

        if (i >= 2) {
            const int p = m - 1;
            const bool ir = (p >= 1) && (p <= H_IMG - 2);
            unsigned wn = 0, sn = 0;

            // q = 0
            {
                float ag = fabsf(gC0), ah = fabsf(hC0), mg = mC0;
                float n1, n2;
                if (ah < ag * T1)      { n1 = mC1;  n2 = mCm1; }
                else if (ah > ag * T2) { n1 = mU0;  n2 = m0;   }
                else if (gC0 * hC0 > 0.0f) { n1 = mU1;  n2 = mm1; }
                else                   { n1 = mUm1; n2 = m1;   }
                bool keep = ir && ic0 && (mg >= n1) && (mg > n2);
                if (keep && mg > 100.0f) { wn |= 1u; if (mg > 200.0f) sn |= 1u; }
            }
            // q = 1
            {
                float ag = fabsf(gC1), ah = fabsf(hC1), mg = mC1;
                float n1, n2;
                if (ah < ag * T1)      { n1 = mC2; n2 = mC0; }
                else if (ah > ag * T2) { n1 = mU1; n2 = m1;  }
                else if (gC1 * hC1 > 0.0f) { n1 = mU2; n2 = m0; }
                else                   { n1 = mU0; n2 = m2;  }
                bool keep = ir && (mg >= n1) && (mg > n2);
                if (keep && mg > 100.0f) { wn |= 2u; if (mg > 200.0f) sn |= 2u; }
            }
            // q = 2
            {
                float ag = fabsf(gC2), ah = fabsf(hC2), mg = mC2;
                float n1, n2;
                if (ah < ag * T1)      { n1 = mC3; n2 = mC1; }
                else if (ah > ag * T2) { n1 = mU2; n2 = m2;  }
                else if (gC2 * hC2 > 0.0f) { n1 = mU3; n2 = m1; }
                else                   { n1 = mU1; n2 = m3;  }
                bool keep = ir && (mg >= n1) && (mg > n2);
                if (keep && mg > 100.0f) { wn |= 4u; if (mg > 200.0f) sn |= 4u; }
            }
            // q = 3
            {
                float ag = fabsf(gC3), ah = fabsf(hC3), mg = mC3;
                float n1, n2;
                if (ah < ag * T1)      { n1 = mCp4; n2 = mC2; }
                else if (ah > ag * T2) { n1 = mU3;  n2 = m3;  }
                else if (gC3 * hC3 > 0.0f) { n1 = mUp4; n2 = m2; }
                else                   { n1 = mU2;  n2 = mp4; }
                bool keep = ir && ic3 && (mg >= n1) && (mg > n2);
                if (keep && mg > 100.0f) { wn |= 8u; if (mg > 200.0f) sn |= 8u; }
            }

            // assemble 32-bit words across groups of 8 lanes
            unsigned sh = (lane & 7) * 4;
            unsigned wv = wn << sh, sv = sn << sh;
            wv |= __shfl_xor_sync(FULL, wv, 1);
            sv |= __shfl_xor_sync(FULL, sv, 1);
            wv |= __shfl_xor_sync(FULL, wv, 2);
            sv |= __shfl_xor_sync(FULL, sv, 2);
            wv |= __shfl_xor_sync(FULL, wv, 4);
            sv |= __shfl_xor_sync(FULL, sv, 4);
            if ((lane & 7) == 0) {
                int wi = p * WW + strip * 4 + (lane >> 3);
                g_W[wi] = wv;
                g_E[wi] = sv;
            }
        }

        // rotate pipelines
        mUm1 = mCm1; mU0 = mC0; mU1 = mC1; mU2 = mC2; mU3 = mC3; mUp4 = mCp4;
        mCm1 = mm1;  mC0 = m0;  mC1 = m1;  mC2 = m2;  mC3 = m3;  mCp4 = mp4;
        gC0 = gx0; gC1 = gx1; gC2 = gx2; gC3 = gx3;
        hC0 = gy0; hC1 = gy1; hC2 = gy2; hC3 = gy3;
        A = B; B = C; C = N;
        Ah0 = Bh0; Bh0 = Ch0; Ch0 = Nh0;
        Ah1 = Bh1; Bh1 = Ch1; Ch1 = Nh1;
    }
}

// ---------------------------------------------------------------------------
// K2: persistent cooperative hysteresis (R5 version). 64 blocks, 32-row bands.
// ---------------------------------------------------------------------------
#define BAND 32
#define NB (H_IMG / BAND)   // 64

__device__ __forceinline__ void grid_barrier() {
    __syncthreads();
    if (threadIdx.x == 0) {
        __threadfence();
        unsigned gen = *(volatile unsigned*)&g_bar_gen;
        unsigned a = atomicAdd(&g_bar_arrive, 1u);
        if (a == NB - 1) {
            g_bar_arrive = 0u;
            __threadfence();
            atomicAdd(&g_bar_gen, 1u);
        } else {
            while (*(volatile unsigned*)&g_bar_gen == gen) __nanosleep(20);
        }
        __threadfence();
    }
    __syncthreads();
}

__global__ __launch_bounds__(1024, 1) void k_hyst() {
    __shared__ unsigned sE[BAND + 2][WW + 2];

    const int tid = threadIdx.x;
    const int q = tid >> 6, c = tid & 63;
    const int cc = c + 1;
    const int R = q * 2 + 1;
    const int r0 = blockIdx.x * BAND;
    const int gw = (r0 + q * 2) * WW + c;

    if (tid < BAND + 2) { sE[tid][0] = 0u; sE[tid][WW + 1] = 0u; }
    if (tid < WW) { sE[0][tid + 1] = 0u; sE[BAND + 1][tid + 1] = 0u; }

    unsigned a = g_E[gw];
    unsigned b = g_E[gw + WW];
    const unsigned W0 = g_W[gw];
    const unsigned W1 = g_W[gw + WW];
    sE[R][cc] = a; sE[R + 1][cc] = b;
    __syncthreads();

    auto pass = [&]() -> int {
        unsigned dU = dilw(sE[R - 1][cc - 1], sE[R - 1][cc], sE[R - 1][cc + 1]);
        unsigned dD = dilw(sE[R + 2][cc - 1], sE[R + 2][cc], sE[R + 2][cc + 1]);
        unsigned hA = dilw(sE[R][cc - 1],     a,             sE[R][cc + 1]);
        unsigned hB = dilw(sE[R + 1][cc - 1], b,             sE[R + 1][cc + 1]);
        unsigned na = hclose(a | (W0 & (dU | hA | hB)), W0);
        unsigned hA2 = dilw(sE[R][cc - 1], na, sE[R][cc + 1]);
        unsigned nb = hclose(b | (W1 & (hA2 | hB | dD)), W1);
        unsigned hB2 = dilw(sE[R + 1][cc - 1], nb, sE[R + 1][cc + 1]);
        unsigned na2 = hclose(na | (W0 & (dU | hA2 | hB2)), W0);
        int ch = (na2 != a) | (nb != b);
        if (na2 != a) { a = na2; sE[R][cc] = a; }
        if (nb != b)  { b = nb;  sE[R + 1][cc] = b; }
        return __syncthreads_or(ch);
    };

    while (pass()) {}

    for (int p = 0;; p ^= 1) {
        if (q == 0)      *(volatile unsigned*)&g_E[r0 * WW + c] = a;
        if (q == 15)     *(volatile unsigned*)&g_E[(r0 + BAND - 1) * WW + c] = b;
        grid_barrier();
        if (tid < WW) {
            sE[0][tid + 1] = (r0 > 0) ? *(volatile unsigned*)&g_E[(r0 - 1) * WW + tid] : 0u;
            sE[BAND + 1][tid + 1] = (r0 + BAND < H_IMG)
                ? *(volatile unsigned*)&g_E[(r0 + BAND) * WW + tid] : 0u;
        }
        __syncthreads();

        int changed = pass();
        if (changed) {
            atomicOr(&g_flag[p], 1u);
            while (pass()) {}
        }
        grid_barrier();
        unsigned f = *(volatile unsigned*)&g_flag[p];
        if (blockIdx.x == 0 && tid == 0) g_flag[p ^ 1] = 0u;
        if (!f) break;
    }

    g_E[gw] = a;
    g_E[gw + WW] = b;
}

// ---------------------------------------------------------------------------
// K3: expand edge bitmask -> 3 x H x W float via smem staging + TMA bulk.
// ---------------------------------------------------------------------------
#define WRB 2

__global__ __launch_bounds__(256) void k_write(float* __restrict__ out) {
    __shared__ __align__(16) float4 sbuf[WRB * 512];   // 16 KB

    const int r0 = blockIdx.x * WRB;
    const int t = threadIdx.x;

#pragma unroll
    for (int k = 0; k < WRB * 2; k++) {
        int f = t + k * 256;
        int row = f >> 9;
        int x4 = f & 511;
        unsigned w = g_E[(r0 + row) * WW + (x4 >> 3)];
        unsigned bits = (w >> ((x4 & 7u) * 4u)) & 0xFu;
        float4 v;
        v.x = (bits & 1u) ? 1.0f : 0.0f;
        v.y = (bits & 2u) ? 1.0f : 0.0f;
        v.z = (bits & 4u) ? 1.0f : 0.0f;
        v.w = (bits & 8u) ? 1.0f : 0.0f;
        sbuf[f] = v;
    }
    __syncthreads();

    if (t == 0) {
        asm volatile("fence.proxy.async.shared::cta;" ::: "memory");
        unsigned saddr = (unsigned)__cvta_generic_to_shared(sbuf);
#pragma unroll
        for (int plane = 0; plane < 3; plane++) {
            float* dst = out + (size_t)plane * NPIX + (size_t)r0 * W_IMG;
            asm volatile(
                "cp.async.bulk.global.shared::cta.bulk_group [%0], [%1], %2;"
                :: "l"(dst), "r"(saddr), "n"(WRB * W_IMG * 4) : "memory");
        }
        asm volatile("cp.async.bulk.commit_group;" ::: "memory");
        asm volatile("cp.async.bulk.wait_group 0;" ::: "memory");
    }
}

// ---------------------------------------------------------------------------
extern "C" void kernel_launch(void* const* d_in, const int* in_sizes, int n_in,
                              void* d_out, int out_size) {
    const float* x = (const float*)d_in[0];
    float* out = (float*)d_out;

    k_grad<<<512, 256>>>(x);
    k_hyst<<<NB, 1024>>>();
    k_write<<<H_IMG / WRB, 256>>>(out);
}